// round 6
// baseline (speedup 1.0000x reference)
#include <cuda_runtime.h>

// LoRALayerNorm: x [B=2, S=4096, N=8192] fp32, single fused persistent kernel.
// Each CTA: (phase 0) computes scale/shift vectors into smem from the rank-4
// LoRA factors (A/B tensors are 512KB total -> L2-hot), then (phase 1) loops
// over its rows with a double-buffered register pipeline: the next row's
// 4 LDG.128/thread are in flight across the current row's reduce barrier and
// epilogue, so the DRAM stream never drains.

#define N_FEAT 8192
#define N_ROWS 8192
#define RANK 4
#define SCALING_F 2.0f   // ALPHA/RANK = 8/4
#define EPS_F 1e-5f

#define TPB 512
#define VPT 4                    // float4 per thread per row: 512*4*4 = 8192
#define GRID_CTAS (148 * 2)      // persistent: 2 CTAs per SM

#define SMEM_BYTES (2 * N_FEAT * 4)   // sc[8192] + sh[8192] floats = 64KB

__global__ __launch_bounds__(TPB, 2)
void lora_layernorm_fused_kernel(const float* __restrict__ x,
                                 const float* __restrict__ sA,
                                 const float* __restrict__ sB,
                                 const float* __restrict__ hA,
                                 const float* __restrict__ hB,
                                 float* __restrict__ out) {
    extern __shared__ float smem[];
    float* s_sc = smem;             // [N_FEAT]
    float* s_sh = smem + N_FEAT;    // [N_FEAT]
    __shared__ float s_red[4][TPB / 32];
    __shared__ float s_tot[4];

    const int tid = threadIdx.x;
    const int wid = tid >> 5;
    const int lane = tid & 31;

    // ---- Phase 0: scale/shift vectors into smem (L2-hot rank-4 factors) ----
#pragma unroll
    for (int k = 0; k < N_FEAT / TPB; k++) {
        const int i = tid + k * TPB;
        float4 a_s = __ldg(reinterpret_cast<const float4*>(sA + i * RANK));
        float4 a_h = __ldg(reinterpret_cast<const float4*>(hA + i * RANK));
        float sc = a_s.x * __ldg(&sB[0 * N_FEAT + i])
                 + a_s.y * __ldg(&sB[1 * N_FEAT + i])
                 + a_s.z * __ldg(&sB[2 * N_FEAT + i])
                 + a_s.w * __ldg(&sB[3 * N_FEAT + i]);
        float sh = a_h.x * __ldg(&hB[0 * N_FEAT + i])
                 + a_h.y * __ldg(&hB[1 * N_FEAT + i])
                 + a_h.z * __ldg(&hB[2 * N_FEAT + i])
                 + a_h.w * __ldg(&hB[3 * N_FEAT + i]);
        s_sc[i] = sc * SCALING_F;
        s_sh[i] = sh * SCALING_F;
    }
    __syncthreads();

    const float4* scv = reinterpret_cast<const float4*>(s_sc);
    const float4* shv = reinterpret_cast<const float4*>(s_sh);

    // ---- Phase 1: persistent row loop, double-buffered registers ----
    int row = blockIdx.x;
    float4 v[VPT], w[VPT];
    {
        const float4* xr = reinterpret_cast<const float4*>(x + (size_t)row * N_FEAT);
#pragma unroll
        for (int k = 0; k < VPT; k++) v[k] = __ldcs(&xr[tid + k * TPB]);
    }

    while (row < N_ROWS) {
        const int nrow = row + GRID_CTAS;
        // Issue next row's loads BEFORE this row's barrier: they stay in
        // flight through the reduction and epilogue.
        if (nrow < N_ROWS) {
            const float4* xn = reinterpret_cast<const float4*>(x + (size_t)nrow * N_FEAT);
#pragma unroll
            for (int k = 0; k < VPT; k++) w[k] = __ldcs(&xn[tid + k * TPB]);
        }

        float s = 0.f, q = 0.f;
#pragma unroll
        for (int k = 0; k < VPT; k++) {
            float4 t = v[k];
            s += t.x + t.y + t.z + t.w;
            q += t.x * t.x + t.y * t.y + t.z * t.z + t.w * t.w;
        }
#pragma unroll
        for (int off = 16; off > 0; off >>= 1) {
            s += __shfl_xor_sync(0xffffffffu, s, off);
            q += __shfl_xor_sync(0xffffffffu, q, off);
        }
        if (lane == 0) {
            s_red[0][wid] = s;
            s_red[1][wid] = q;
        }
        __syncthreads();
        if (wid == 0) {
            float a = (lane < TPB / 32) ? s_red[0][lane] : 0.0f;
            float b = (lane < TPB / 32) ? s_red[1][lane] : 0.0f;
#pragma unroll
            for (int off = 8; off > 0; off >>= 1) {
                a += __shfl_xor_sync(0xffffffffu, a, off);
                b += __shfl_xor_sync(0xffffffffu, b, off);
            }
            if (lane == 0) {
                s_tot[0] = a;
                s_tot[1] = b;
            }
        }
        __syncthreads();

        const float invN = 1.0f / N_FEAT;
        const float mean = s_tot[0] * invN;
        const float rstd = rsqrtf(s_tot[1] * invN - mean * mean + EPS_F);

        float4* orow = reinterpret_cast<float4*>(out + (size_t)row * N_FEAT);
#pragma unroll
        for (int k = 0; k < VPT; k++) {
            const int idx = tid + k * TPB;
            float4 sc = scv[idx];
            float4 sh = shv[idx];
            float4 t = v[k];
            float4 o;
            o.x = (t.x - mean) * rstd * sc.x + sh.x;
            o.y = (t.y - mean) * rstd * sc.y + sh.y;
            o.z = (t.z - mean) * rstd * sc.z + sh.z;
            o.w = (t.w - mean) * rstd * sc.w + sh.w;
            __stcs(&orow[idx], o);
        }

#pragma unroll
        for (int k = 0; k < VPT; k++) v[k] = w[k];
        row = nrow;
    }
}

// ---------------------------------------------------------------------------
extern "C" void kernel_launch(void* const* d_in, const int* in_sizes, int n_in,
                              void* d_out, int out_size) {
    const float* x = (const float*)d_in[0];
    const float* sA = (const float*)d_in[1];
    const float* sB = (const float*)d_in[2];
    const float* hA = (const float*)d_in[3];
    const float* hB = (const float*)d_in[4];
    float* out = (float*)d_out;

    cudaFuncSetAttribute(lora_layernorm_fused_kernel,
                         cudaFuncAttributeMaxDynamicSharedMemorySize, SMEM_BYTES);
    lora_layernorm_fused_kernel<<<GRID_CTAS, TPB, SMEM_BYTES>>>(x, sA, sB, hA, hB, out);
}

// round 7
// speedup vs baseline: 1.0792x; 1.0792x over previous
#include <cuda_runtime.h>

// LoRALayerNorm: x [B=2, S=4096, N=8192] fp32 — single-launch fused kernel.
// Phase 0: first 16 CTAs compute the rank-4 diag scale/shift vectors ONCE into
//          device globals (512KB of A/B reads total, not per-CTA).
// Grid barrier: epoch-based atomic counter (all 296 CTAs resident -> safe).
// Phase 1: persistent row loop, register-resident single-pass layernorm
//          (identical body to the best 77.5us two-kernel version).

#define N_FEAT 8192
#define N_ROWS 8192
#define RANK 4
#define SCALING_F 2.0f   // ALPHA/RANK = 8/4
#define EPS_F 1e-5f

#define TPB 512
#define VPT 4                  // float4 per thread per row: 512*4*4 = 8192
#define GRID_CTAS (148 * 2)    // all resident at 2 CTAs/SM

__device__ float g_scale[N_FEAT];
__device__ float g_shift[N_FEAT];
__device__ unsigned int g_counter = 0;   // monotonic across launches (epoch barrier)

__global__ __launch_bounds__(TPB, 2)
void lora_layernorm_fused_kernel(const float* __restrict__ x,
                                 const float* __restrict__ sA,
                                 const float* __restrict__ sB,
                                 const float* __restrict__ hA,
                                 const float* __restrict__ hB,
                                 float* __restrict__ out) {
    const int tid = threadIdx.x;
    const int wid = tid >> 5;
    const int lane = tid & 31;

    // ---- Phase 0: 16 CTAs cover all 8192 features exactly once ----
    const int gid = blockIdx.x * TPB + tid;
    if (gid < N_FEAT) {
        float4 a_s = __ldg(reinterpret_cast<const float4*>(sA + gid * RANK));
        float4 a_h = __ldg(reinterpret_cast<const float4*>(hA + gid * RANK));
        float sc = a_s.x * __ldg(&sB[0 * N_FEAT + gid])
                 + a_s.y * __ldg(&sB[1 * N_FEAT + gid])
                 + a_s.z * __ldg(&sB[2 * N_FEAT + gid])
                 + a_s.w * __ldg(&sB[3 * N_FEAT + gid]);
        float sh = a_h.x * __ldg(&hB[0 * N_FEAT + gid])
                 + a_h.y * __ldg(&hB[1 * N_FEAT + gid])
                 + a_h.z * __ldg(&hB[2 * N_FEAT + gid])
                 + a_h.w * __ldg(&hB[3 * N_FEAT + gid]);
        g_scale[gid] = sc * SCALING_F;
        g_shift[gid] = sh * SCALING_F;
    }
    __syncthreads();

    // ---- Grid barrier (epoch-based; counter grows monotonically) ----
    __shared__ unsigned int s_go;
    if (tid == 0) {
        __threadfence();   // release g_scale/g_shift writes
        unsigned int old = atomicAdd(&g_counter, 1u);
        unsigned int target = old - (old % GRID_CTAS) + GRID_CTAS;
        while (atomicAdd(&g_counter, 0u) < target) { }
        __threadfence();   // acquire
        s_go = 1u;
    }
    __syncthreads();
    (void)s_go;

    // ---- Phase 1: persistent row loop (register-resident single pass) ----
    __shared__ float s_sum[TPB / 32];
    __shared__ float s_sumsq[TPB / 32];
    __shared__ float s_mean, s_rstd;
    const float4* scv = reinterpret_cast<const float4*>(g_scale);
    const float4* shv = reinterpret_cast<const float4*>(g_shift);

    for (int row = blockIdx.x; row < N_ROWS; row += GRID_CTAS) {
        const float4* xrow = reinterpret_cast<const float4*>(x + (size_t)row * N_FEAT);
        float4* orow = reinterpret_cast<float4*>(out + (size_t)row * N_FEAT);

        float4 v[VPT];
        float sum = 0.0f, sumsq = 0.0f;
#pragma unroll
        for (int k = 0; k < VPT; k++) {
            float4 t = __ldcs(&xrow[tid + k * TPB]);
            v[k] = t;
            sum += t.x + t.y + t.z + t.w;
            sumsq += t.x * t.x + t.y * t.y + t.z * t.z + t.w * t.w;
        }

#pragma unroll
        for (int off = 16; off > 0; off >>= 1) {
            sum += __shfl_xor_sync(0xffffffffu, sum, off);
            sumsq += __shfl_xor_sync(0xffffffffu, sumsq, off);
        }
        if (lane == 0) {
            s_sum[wid] = sum;
            s_sumsq[wid] = sumsq;
        }
        __syncthreads();
        if (wid == 0) {
            float a = (lane < TPB / 32) ? s_sum[lane] : 0.0f;
            float b = (lane < TPB / 32) ? s_sumsq[lane] : 0.0f;
#pragma unroll
            for (int off = 8; off > 0; off >>= 1) {
                a += __shfl_xor_sync(0xffffffffu, a, off);
                b += __shfl_xor_sync(0xffffffffu, b, off);
            }
            if (lane == 0) {
                float mean = a * (1.0f / N_FEAT);
                float var = b * (1.0f / N_FEAT) - mean * mean;
                s_mean = mean;
                s_rstd = rsqrtf(var + EPS_F);
            }
        }
        __syncthreads();
        const float mean = s_mean;
        const float rstd = s_rstd;

#pragma unroll
        for (int k = 0; k < VPT; k++) {
            const int idx = tid + k * TPB;
            float4 sc = __ldg(&scv[idx]);
            float4 sh = __ldg(&shv[idx]);
            float4 t = v[k];
            float4 o;
            o.x = (t.x - mean) * rstd * sc.x + sh.x;
            o.y = (t.y - mean) * rstd * sc.y + sh.y;
            o.z = (t.z - mean) * rstd * sc.z + sh.z;
            o.w = (t.w - mean) * rstd * sc.w + sh.w;
            __stcs(&orow[idx], o);
        }
        __syncthreads();   // protect s_mean/s_rstd before next iteration
    }
}

// ---------------------------------------------------------------------------
extern "C" void kernel_launch(void* const* d_in, const int* in_sizes, int n_in,
                              void* d_out, int out_size) {
    const float* x = (const float*)d_in[0];
    const float* sA = (const float*)d_in[1];
    const float* sB = (const float*)d_in[2];
    const float* hA = (const float*)d_in[3];
    const float* hB = (const float*)d_in[4];
    float* out = (float*)d_out;

    lora_layernorm_fused_kernel<<<GRID_CTAS, TPB>>>(x, sA, sB, hA, hB, out);
}

// round 8
// speedup vs baseline: 1.1949x; 1.1071x over previous
#include <cuda_runtime.h>

// LoRALayerNorm: x [B=2, S=4096, N=8192] fp32.
// Two kernels overlapped via PDL (programmatic dependent launch):
//   k1 (16 CTAs): rank-4 diag -> g_scale/g_shift, triggers early launch.
//   k2 (8192 CTAs): register-resident single-pass layernorm; starts its x
//      loads while k1 is still running and only waits on k1 (grid dep sync)
//      right before the epilogue first touches scale/shift.

#define N_FEAT 8192
#define N_ROWS 8192
#define RANK 4
#define SCALING_F 2.0f   // ALPHA/RANK = 8/4
#define EPS_F 1e-5f

#define TPB 512
#define VPT 4            // float4 per thread: 512*4*4 = 8192 floats per row

__device__ float g_scale[N_FEAT];
__device__ float g_shift[N_FEAT];

// ---------------------------------------------------------------------------
// Kernel 1: low-rank diagonal -> scale/shift vectors
// ---------------------------------------------------------------------------
__global__ void compute_vectors_kernel(const float* __restrict__ sA,
                                       const float* __restrict__ sB,
                                       const float* __restrict__ hA,
                                       const float* __restrict__ hB) {
    // Let the dependent grid begin launching immediately; correctness is
    // guarded by cudaGridDependencySynchronize() in kernel 2.
    cudaTriggerProgrammaticLaunchCompletion();

    int i = blockIdx.x * blockDim.x + threadIdx.x;
    if (i >= N_FEAT) return;
    float4 a_s = __ldg(reinterpret_cast<const float4*>(sA + i * RANK));
    float4 a_h = __ldg(reinterpret_cast<const float4*>(hA + i * RANK));
    float sc = a_s.x * __ldg(&sB[0 * N_FEAT + i])
             + a_s.y * __ldg(&sB[1 * N_FEAT + i])
             + a_s.z * __ldg(&sB[2 * N_FEAT + i])
             + a_s.w * __ldg(&sB[3 * N_FEAT + i]);
    float sh = a_h.x * __ldg(&hB[0 * N_FEAT + i])
             + a_h.y * __ldg(&hB[1 * N_FEAT + i])
             + a_h.z * __ldg(&hB[2 * N_FEAT + i])
             + a_h.w * __ldg(&hB[3 * N_FEAT + i]);
    g_scale[i] = sc * SCALING_F;
    g_shift[i] = sh * SCALING_F;
}

// ---------------------------------------------------------------------------
// Kernel 2: one CTA per row, register-resident single-pass layernorm (R3 body)
// ---------------------------------------------------------------------------
__global__ __launch_bounds__(TPB, 3)
void lora_layernorm_kernel(const float* __restrict__ x,
                           float* __restrict__ out) {
    const int row = blockIdx.x;
    const int tid = threadIdx.x;
    const float4* xrow = reinterpret_cast<const float4*>(x + (size_t)row * N_FEAT);
    float4* orow = reinterpret_cast<float4*>(out + (size_t)row * N_FEAT);

    // Streaming loads of x — independent of kernel 1, so they overlap it.
    float4 v[VPT];
    float sum = 0.0f, sumsq = 0.0f;
#pragma unroll
    for (int k = 0; k < VPT; k++) {
        float4 t = __ldcs(&xrow[tid + k * TPB]);
        v[k] = t;
        sum += t.x + t.y + t.z + t.w;
        sumsq += t.x * t.x + t.y * t.y + t.z * t.z + t.w * t.w;
    }

#pragma unroll
    for (int off = 16; off > 0; off >>= 1) {
        sum += __shfl_xor_sync(0xffffffffu, sum, off);
        sumsq += __shfl_xor_sync(0xffffffffu, sumsq, off);
    }

    __shared__ float s_sum[TPB / 32];
    __shared__ float s_sumsq[TPB / 32];
    __shared__ float s_mean, s_rstd;
    const int wid = tid >> 5;
    const int lane = tid & 31;
    if (lane == 0) {
        s_sum[wid] = sum;
        s_sumsq[wid] = sumsq;
    }
    __syncthreads();
    if (wid == 0) {
        float a = (lane < TPB / 32) ? s_sum[lane] : 0.0f;
        float b = (lane < TPB / 32) ? s_sumsq[lane] : 0.0f;
#pragma unroll
        for (int off = 8; off > 0; off >>= 1) {
            a += __shfl_xor_sync(0xffffffffu, a, off);
            b += __shfl_xor_sync(0xffffffffu, b, off);
        }
        if (lane == 0) {
            float mean = a * (1.0f / N_FEAT);
            float var = b * (1.0f / N_FEAT) - mean * mean;
            s_mean = mean;
            s_rstd = rsqrtf(var + EPS_F);
        }
    }
    __syncthreads();
    const float mean = s_mean;
    const float rstd = s_rstd;

    // Wait for kernel 1's g_scale/g_shift writes to be visible (first and
    // only point of dependency).
    cudaGridDependencySynchronize();

    const float4* scv = reinterpret_cast<const float4*>(g_scale);
    const float4* shv = reinterpret_cast<const float4*>(g_shift);
#pragma unroll
    for (int k = 0; k < VPT; k++) {
        const int idx = tid + k * TPB;
        float4 sc = __ldg(&scv[idx]);
        float4 sh = __ldg(&shv[idx]);
        float4 t = v[k];
        float4 o;
        o.x = (t.x - mean) * rstd * sc.x + sh.x;
        o.y = (t.y - mean) * rstd * sc.y + sh.y;
        o.z = (t.z - mean) * rstd * sc.z + sh.z;
        o.w = (t.w - mean) * rstd * sc.w + sh.w;
        __stcs(&orow[idx], o);
    }
}

// ---------------------------------------------------------------------------
extern "C" void kernel_launch(void* const* d_in, const int* in_sizes, int n_in,
                              void* d_out, int out_size) {
    const float* x = (const float*)d_in[0];
    const float* sA = (const float*)d_in[1];
    const float* sB = (const float*)d_in[2];
    const float* hA = (const float*)d_in[3];
    const float* hB = (const float*)d_in[4];
    float* out = (float*)d_out;

    compute_vectors_kernel<<<N_FEAT / TPB, TPB>>>(sA, sB, hA, hB);

    // Launch kernel 2 with programmatic stream serialization: it may begin
    // while kernel 1 is still resident; the grid-dep sync inside provides
    // the ordering on g_scale/g_shift.
    cudaLaunchConfig_t cfg = {};
    cfg.gridDim = dim3(N_ROWS, 1, 1);
    cfg.blockDim = dim3(TPB, 1, 1);
    cfg.dynamicSmemBytes = 0;
    cfg.stream = 0;
    cudaLaunchAttribute attr[1];
    attr[0].id = cudaLaunchAttributeProgrammaticStreamSerialization;
    attr[0].val.programmaticStreamSerializationAllowed = 1;
    cfg.attrs = attr;
    cfg.numAttrs = 1;
    cudaLaunchKernelEx(&cfg, lora_layernorm_kernel, x, out);
}